// round 10
// baseline (speedup 1.0000x reference)
#include <cuda_runtime.h>
#include <math.h>

#define Nn   50000
#define Ee   800000
#define Bb   4096
#define EPSc 0.3f
#define NEGc 0.3f

// ---------------- static device scratch (no allocs allowed) ----------------
__device__ __align__(16) float g_x[Nn * 64];          // raw1 = leaky(h@t1)
__device__ __align__(16) float g_raw2[Nn * 192];      // concat(h1_1..3)
__device__ int    g_deg[3][Nn];
__device__ int    g_off[3][Nn];
__device__ int    g_cur[3][Nn];
__device__ int    g_esrc[3][Ee];
__device__ float  g_d[3][Nn];
__device__ float  g_s1dst[3][Nn];
__device__ float  g_s2dst[3][Nn];
__device__ __align__(8) float2 g_sd1[3][Nn];   // (s1src, d)
__device__ __align__(8) float2 g_sd2[3][Nn];   // (s2src, d)
__device__ __align__(16) float g_final[Bb * 192];  // h2 part only

__device__ __forceinline__ float lk(float x) { return x >= 0.f ? x : NEGc * x; }

// ---- packed f32x2 helpers (FFMA2: only reachable via PTX fma.rn.f32x2) ----
__device__ __forceinline__ void fma2(unsigned long long& d, unsigned long long a,
                                     unsigned long long b) {
    asm("fma.rn.f32x2 %0, %1, %2, %0;" : "+l"(d) : "l"(a), "l"(b));
}
__device__ __forceinline__ unsigned long long pack2(float lo, float hi) {
    unsigned long long r;
    asm("mov.b64 %0, {%1, %2};" : "=l"(r) : "f"(lo), "f"(hi));
    return r;
}
__device__ __forceinline__ void unpack2(unsigned long long v, float& lo, float& hi) {
    asm("mov.b64 {%0, %1}, %2;" : "=f"(lo), "=f"(hi) : "l"(v));
}

// ---------------- zero degree counters ----------------
__global__ void k_zero0() {
    int i = blockIdx.x * blockDim.x + threadIdx.x;
    int stride = gridDim.x * blockDim.x;
    int* dp = &g_deg[0][0];
    for (int j = i; j < 3 * Nn; j += stride) dp[j] = 0;
}

// ---------------- degree count ----------------
__global__ void k_deg2(const int* __restrict__ d1, const int* __restrict__ d2,
                       const int* __restrict__ d3) {
    long i = (long)blockIdx.x * blockDim.x + threadIdx.x;
    long stride = (long)gridDim.x * blockDim.x;
    for (long idx = i; idx < 3L * Ee; idx += stride) {
        int set = (int)(idx / Ee);
        int j = (int)(idx - (long)set * Ee);
        const int* dp = set == 0 ? d1 : set == 1 ? d2 : d3;
        atomicAdd(&g_deg[set][__ldg(dp + j)], 1);
    }
}

// ---------------- CSR offsets (block-wise prefix scan) + dnorm --------------
__global__ void k_csr() {
    int set = blockIdx.x;      // 3 blocks, 1024 threads
    __shared__ int wsum[32];
    __shared__ int carry_s;
    int tid = threadIdx.x;
    int lane = tid & 31, wid = tid >> 5;
    if (tid == 0) carry_s = 0;
    __syncthreads();
    for (int base = 0; base < Nn; base += 1024) {
        int i = base + tid;
        int v = (i < Nn) ? g_deg[set][i] : 0;
        int p = v;
        #pragma unroll
        for (int off = 1; off < 32; off <<= 1) {
            int t = __shfl_up_sync(0xFFFFFFFFu, p, off);
            if (lane >= off) p += t;
        }
        if (lane == 31) wsum[wid] = p;
        __syncthreads();
        if (wid == 0) {
            int s = wsum[lane];
            #pragma unroll
            for (int off = 1; off < 32; off <<= 1) {
                int t = __shfl_up_sync(0xFFFFFFFFu, s, off);
                if (lane >= off) s += t;
            }
            wsum[lane] = s;
        }
        __syncthreads();
        int woff = wid ? wsum[wid - 1] : 0;
        int excl = carry_s + woff + p - v;
        if (i < Nn) {
            g_off[set][i] = excl;
            g_cur[set][i] = excl;
            g_d[set][i] = v > 0 ? rsqrtf((float)v) : 0.f;
        }
        __syncthreads();
        if (tid == 0) carry_s += wsum[31];
        __syncthreads();
    }
}

// ---------------- CSR fill: scatter src ids by dst ----------------
__global__ void k_fill(const int* __restrict__ s1, const int* __restrict__ d1,
                       const int* __restrict__ s2, const int* __restrict__ d2,
                       const int* __restrict__ s3, const int* __restrict__ d3) {
    long i = (long)blockIdx.x * blockDim.x + threadIdx.x;
    long stride = (long)gridDim.x * blockDim.x;
    for (long idx = i; idx < 3L * Ee; idx += stride) {
        int set = (int)(idx / Ee);
        int j = (int)(idx - (long)set * Ee);
        const int* sp = set == 0 ? s1 : set == 1 ? s2 : s3;
        const int* dp = set == 0 ? d1 : set == 1 ? d2 : d3;
        int s = __ldg(sp + j);
        int dd = __ldg(dp + j);
        int pos = atomicAdd(&g_cur[set][dd], 1);
        g_esrc[set][pos] = s;
    }
}

// ---------------- t1: x = leaky(h @ t1_w^T + b) — 8x8 f32x2 tiling ---------
// block 256 thr -> 256 nodes x 64 outs; thread = 4 node-pairs x 8 outs.
// LDS per k per thread: 4x LDS.128 = 64B per 128 FMA = 0.5 B/FMA.
#define T1_SH_STR 264
#define T1_SW_STR 72
__global__ void __launch_bounds__(256, 2)
k_t1(const float* __restrict__ h, const float* __restrict__ w,
     const float* __restrict__ bias) {
    extern __shared__ float sm[];
    float* sh = sm;                    // [32][264]  sh[k][node]
    float* sW = sm + 32 * T1_SH_STR;   // [32][72]   sW[k][o]
    int tid = threadIdx.x;
    int tx = tid & 7, ty = tid >> 3;   // tx: out group (8 outs), ty: node group (8)
    int ob = tx * 8;
    int nb = blockIdx.x * 256;
    unsigned long long acc[4][8];      // [nodepair][out]
    #pragma unroll
    for (int o = 0; o < 8; o++) {
        float b = bias[ob + o];
        unsigned long long bb = pack2(b, b);
        #pragma unroll
        for (int j = 0; j < 4; j++) acc[j][o] = bb;
    }
    int kq = (tid & 7) * 4;            // k-quad for h loads
    for (int k0 = 0; k0 < 256; k0 += 32) {
        __syncthreads();
        // load h chunk transposed: sh[k][n_local], 8 rows per thread
        #pragma unroll
        for (int p = 0; p < 8; p++) {
            int nl = p * 32 + ty;      // ty doubles as row selector 0..31
            int n = nb + nl;
            float4 hv = make_float4(0.f, 0.f, 0.f, 0.f);
            if (n < Nn) hv = *(const float4*)(h + (long)n * 256 + k0 + kq);
            sh[(kq + 0) * T1_SH_STR + nl] = hv.x;
            sh[(kq + 1) * T1_SH_STR + nl] = hv.y;
            sh[(kq + 2) * T1_SH_STR + nl] = hv.z;
            sh[(kq + 3) * T1_SH_STR + nl] = hv.w;
        }
        // load W chunk transposed: sW[k][o]   (w is [64][256] row-major)
        {
            int o = tid >> 2;           // 0..63
            int kk = (tid & 3) * 8;     // 0,8,16,24
            float4 wa = *(const float4*)(w + (long)o * 256 + k0 + kk);
            float4 wb = *(const float4*)(w + (long)o * 256 + k0 + kk + 4);
            sW[(kk + 0) * T1_SW_STR + o] = wa.x;
            sW[(kk + 1) * T1_SW_STR + o] = wa.y;
            sW[(kk + 2) * T1_SW_STR + o] = wa.z;
            sW[(kk + 3) * T1_SW_STR + o] = wa.w;
            sW[(kk + 4) * T1_SW_STR + o] = wb.x;
            sW[(kk + 5) * T1_SW_STR + o] = wb.y;
            sW[(kk + 6) * T1_SW_STR + o] = wb.z;
            sW[(kk + 7) * T1_SW_STR + o] = wb.w;
        }
        __syncthreads();
        #pragma unroll 4
        for (int k = 0; k < 32; k++) {
            const float4* wp = (const float4*)(sW + k * T1_SW_STR + ob);
            float4 w0 = wp[0], w1 = wp[1];                 // 2x LDS.128
            unsigned long long wb[8];
            wb[0] = pack2(w0.x, w0.x); wb[1] = pack2(w0.y, w0.y);
            wb[2] = pack2(w0.z, w0.z); wb[3] = pack2(w0.w, w0.w);
            wb[4] = pack2(w1.x, w1.x); wb[5] = pack2(w1.y, w1.y);
            wb[6] = pack2(w1.z, w1.z); wb[7] = pack2(w1.w, w1.w);
            const ulonglong2* hp = (const ulonglong2*)(sh + k * T1_SH_STR + ty * 8);
            ulonglong2 hA = hp[0], hB = hp[1];             // 2x LDS.128
            unsigned long long hh[4] = {hA.x, hA.y, hB.x, hB.y};
            #pragma unroll
            for (int j = 0; j < 4; j++)
                #pragma unroll
                for (int o = 0; o < 8; o++)
                    fma2(acc[j][o], hh[j], wb[o]);
        }
    }
    #pragma unroll
    for (int j = 0; j < 4; j++) {
        float lo[8], hi[8];
        #pragma unroll
        for (int o = 0; o < 8; o++) unpack2(acc[j][o], lo[o], hi[o]);
        int n0 = nb + ty * 8 + j * 2;
        if (n0 < Nn) {
            float4 ra, rb;
            ra.x = lk(lo[0]); ra.y = lk(lo[1]); ra.z = lk(lo[2]); ra.w = lk(lo[3]);
            rb.x = lk(lo[4]); rb.y = lk(lo[5]); rb.z = lk(lo[6]); rb.w = lk(lo[7]);
            *(float4*)(g_x + (long)n0 * 64 + ob) = ra;
            *(float4*)(g_x + (long)n0 * 64 + ob + 4) = rb;
        }
        if (n0 + 1 < Nn) {
            float4 ra, rb;
            ra.x = lk(hi[0]); ra.y = lk(hi[1]); ra.z = lk(hi[2]); ra.w = lk(hi[3]);
            rb.x = lk(hi[4]); rb.y = lk(hi[5]); rb.z = lk(hi[6]); rb.w = lk(hi[7]);
            *(float4*)(g_x + (long)(n0 + 1) * 64 + ob) = ra;
            *(float4*)(g_x + (long)(n0 + 1) * 64 + ob + 4) = rb;
        }
    }
}

// ---------------- per-node gate scalars, layer 1 (D=64) ----------------
__global__ void k_gate1(const float* __restrict__ w0, const float* __restrict__ w1,
                        const float* __restrict__ w2) {
    int gt = blockIdx.x * blockDim.x + threadIdx.x;
    int warp = gt >> 5, lane = gt & 31;
    int nw = (gridDim.x * blockDim.x) >> 5;
    for (int n = warp; n < Nn; n += nw) {
        float x0 = g_x[n * 64 + lane];
        float x1 = g_x[n * 64 + 32 + lane];
        #pragma unroll
        for (int g = 0; g < 3; g++) {
            const float* w = g == 0 ? w0 : g == 1 ? w1 : w2;
            float pd = x0 * w[lane] + x1 * w[32 + lane];
            float ps = x0 * w[64 + lane] + x1 * w[96 + lane];
            #pragma unroll
            for (int off = 16; off; off >>= 1) {
                pd += __shfl_down_sync(0xFFFFFFFFu, pd, off);
                ps += __shfl_down_sync(0xFFFFFFFFu, ps, off);
            }
            if (lane == 0) {
                g_s1dst[g][n] = pd;
                g_sd1[g][n] = make_float2(ps, g_d[g][n]);
            }
        }
    }
}

// ------ fused layer-1: CSR gather-aggregate + hw1 transform -> raw2 ---------
__global__ void __launch_bounds__(256)
k_layer1(const float* __restrict__ hw0, const float* __restrict__ hw1p,
         const float* __restrict__ hw2p, const float* __restrict__ b1,
         const float* __restrict__ b2, const float* __restrict__ b3) {
    extern __shared__ float sm[];
    float* sW = sm;          // [64][64]
    float* su = sm + 4096;   // [8 warps][4][64]
    int set = blockIdx.y;
    const float* w = set == 0 ? hw0 : set == 1 ? hw1p : hw2p;
    float gb = (set == 0 ? b1 : set == 1 ? b2 : b3)[0];
    int tid = threadIdx.x;
    for (int idx = tid; idx < 4096; idx += 256) sW[idx] = w[idx];
    __syncthreads();
    int warp = tid >> 5, lane = tid & 31;
    int nb = blockIdx.x * 32 + warp * 4;
    const float2* x2 = (const float2*)g_x;
    float2 acc[4];
    #pragma unroll
    for (int j = 0; j < 4; j++) { acc[j].x = 0.f; acc[j].y = 0.f; }
    #pragma unroll
    for (int j = 0; j < 4; j++) {
        int n = nb + j;
        if (n >= Nn) continue;
        int deg = g_deg[set][n];
        int off = g_off[set][n];
        float sd = g_s1dst[set][n] + gb;
        float ddn = g_d[set][n];
        for (int base = 0; base < deg; base += 32) {
            int jj = base + lane;
            int src = 0;
            float e = 0.f;
            if (jj < deg) {
                src = __ldg(&g_esrc[set][off + jj]);
                float2 sv = g_sd1[set][src];
                e = tanhf(sd + sv.x) * ddn * sv.y;
            }
            int m = min(32, deg - base);
            int t = 0;
            // 8-wide MLP: batch 8 gathers before FMAs
            for (; t + 8 <= m; t += 8) {
                int sv8[8]; float ev[8]; float2 vv[8];
                #pragma unroll
                for (int q = 0; q < 8; q++) {
                    sv8[q] = __shfl_sync(0xFFFFFFFFu, src, t + q);
                    ev[q]  = __shfl_sync(0xFFFFFFFFu, e, t + q);
                }
                #pragma unroll
                for (int q = 0; q < 8; q++) vv[q] = x2[(long)sv8[q] * 32 + lane];
                #pragma unroll
                for (int q = 0; q < 8; q++) {
                    acc[j].x = fmaf(ev[q], vv[q].x, acc[j].x);
                    acc[j].y = fmaf(ev[q], vv[q].y, acc[j].y);
                }
            }
            for (; t < m; t++) {
                float ee = __shfl_sync(0xFFFFFFFFu, e, t);
                int sj = __shfl_sync(0xFFFFFFFFu, src, t);
                float2 v = x2[(long)sj * 32 + lane];
                acc[j].x = fmaf(ee, v.x, acc[j].x);
                acc[j].y = fmaf(ee, v.y, acc[j].y);
            }
        }
    }
    float* myu = su + warp * 256;
    #pragma unroll
    for (int j = 0; j < 4; j++) {
        int n = nb + j;
        float2 xv = make_float2(0.f, 0.f);
        if (n < Nn) xv = x2[(long)n * 32 + lane];
        myu[j * 64 + 2 * lane]     = EPSc * xv.x + acc[j].x;
        myu[j * 64 + 2 * lane + 1] = EPSc * xv.y + acc[j].y;
    }
    __syncwarp();
    float o[4][2] = {};
    #pragma unroll 8
    for (int k = 0; k < 64; k++) {
        float w0 = sW[k * 64 + lane], w1 = sW[k * 64 + 32 + lane];
        #pragma unroll
        for (int j = 0; j < 4; j++) {
            float uk = myu[j * 64 + k];
            o[j][0] = fmaf(uk, w0, o[j][0]);
            o[j][1] = fmaf(uk, w1, o[j][1]);
        }
    }
    #pragma unroll
    for (int j = 0; j < 4; j++) {
        int n = nb + j;
        if (n < Nn) {
            g_raw2[(long)n * 192 + set * 64 + lane]      = lk(o[j][0]);
            g_raw2[(long)n * 192 + set * 64 + 32 + lane] = lk(o[j][1]);
        }
    }
}

// ---------------- per-node gate scalars, layer 2 (D=192) ----------------
__global__ void k_gate2(const float* __restrict__ w0, const float* __restrict__ w1,
                        const float* __restrict__ w2) {
    int gt = blockIdx.x * blockDim.x + threadIdx.x;
    int warp = gt >> 5, lane = gt & 31;
    int nw = (gridDim.x * blockDim.x) >> 5;
    for (int n = warp; n < Nn; n += nw) {
        float r[6];
        #pragma unroll
        for (int t = 0; t < 6; t++) r[t] = g_raw2[(long)n * 192 + lane + 32 * t];
        #pragma unroll
        for (int g = 0; g < 3; g++) {
            const float* w = g == 0 ? w0 : g == 1 ? w1 : w2;
            float pd = 0.f, ps = 0.f;
            #pragma unroll
            for (int t = 0; t < 6; t++) {
                pd = fmaf(r[t], w[lane + 32 * t], pd);
                ps = fmaf(r[t], w[192 + lane + 32 * t], ps);
            }
            #pragma unroll
            for (int off = 16; off; off >>= 1) {
                pd += __shfl_down_sync(0xFFFFFFFFu, pd, off);
                ps += __shfl_down_sync(0xFFFFFFFFu, ps, off);
            }
            if (lane == 0) {
                g_s2dst[g][n] = pd;
                g_sd2[g][n] = make_float2(ps, g_d[g][n]);
            }
        }
    }
}

// ------ fused layer-2 for SELECTED nodes: CSR gather + hw2 -> final[:,0:192] -
__global__ void k_final_h2(const int* __restrict__ nodes,
                           const float* __restrict__ hw0, const float* __restrict__ hw1p,
                           const float* __restrict__ hw2p, const float* __restrict__ b1,
                           const float* __restrict__ b2, const float* __restrict__ b3) {
    extern __shared__ float sm[];
    float* sW = sm;             // [192][64]
    float* su = sm + 12288;     // [8][192]
    int i = blockIdx.y;
    const float* w = i == 0 ? hw0 : i == 1 ? hw1p : hw2p;
    float gb = (i == 0 ? b1 : i == 1 ? b2 : b3)[0];
    int tid = threadIdx.x;
    for (int idx = tid; idx < 12288; idx += 256) sW[idx] = w[idx];
    __syncthreads();
    int warp = tid >> 5, lane = tid & 31;
    int b = blockIdx.x * 8 + warp;
    int n = nodes[b];
    int deg = g_deg[i][n], off = g_off[i][n];
    float sd = g_s2dst[i][n] + gb;
    float ddn = g_d[i][n];
    float acc[6] = {};
    for (int base = 0; base < deg; base += 32) {
        int jj = base + lane;
        int src = 0;
        float e = 0.f;
        if (jj < deg) {
            src = __ldg(&g_esrc[i][off + jj]);
            float2 sv = g_sd2[i][src];
            e = tanhf(sd + sv.x) * ddn * sv.y;
        }
        int m = min(32, deg - base);
        for (int t = 0; t < m; t++) {
            float ee = __shfl_sync(0xFFFFFFFFu, e, t);
            int sj = __shfl_sync(0xFFFFFFFFu, src, t);
            const float* rp = g_raw2 + (long)sj * 192 + lane;
            #pragma unroll
            for (int q = 0; q < 6; q++)
                acc[q] = fmaf(ee, rp[q * 32], acc[q]);
        }
    }
    #pragma unroll
    for (int q = 0; q < 6; q++) {
        int k = lane + 32 * q;
        su[warp * 192 + k] = EPSc * g_raw2[(long)n * 192 + k] + acc[q];
    }
    __syncwarp();
    float a0 = 0.f, a1 = 0.f;
    #pragma unroll 8
    for (int k = 0; k < 192; k++) {
        float uk = su[warp * 192 + k];
        a0 = fmaf(uk, sW[k * 64 + lane], a0);
        a1 = fmaf(uk, sW[k * 64 + 32 + lane], a1);
    }
    g_final[(long)b * 192 + i * 64 + lane] = lk(a0);
    g_final[(long)b * 192 + i * 64 + 32 + lane] = lk(a1);
}

// ------ s64 = leaky(final @ t2_w^T + b) + fused scores, fused column gather --
__global__ void k_s64(const int* __restrict__ nodes, const float* __restrict__ h,
                      const float* __restrict__ t2w, const float* __restrict__ t2b,
                      const float* __restrict__ t3w, const float* __restrict__ t3b,
                      float* __restrict__ out, int outok) {
    __shared__ float As[32][32];
    __shared__ float Bs[32][65];
    __shared__ float sv[32][65];
    __shared__ int sn[32];
    int tid = threadIdx.x;
    int c = tid & 63, rg = tid >> 6;
    int rows0 = blockIdx.x * 32;
    if (tid < 32) sn[tid] = nodes[rows0 + tid];
    __syncthreads();
    float acc[8];
    #pragma unroll
    for (int r = 0; r < 8; r++) acc[r] = 0.f;
    for (int k0 = 0; k0 < 704; k0 += 32) {
        for (int idx = tid; idx < 1024; idx += 256) {
            int r = idx >> 5, kk = idx & 31;
            float v;
            if (k0 < 192)      v = g_final[(long)(rows0 + r) * 192 + k0 + kk];
            else if (k0 < 448) v = h[(long)sn[r] * 256 + (k0 - 192) + kk];
            else if (k0 < 512) v = g_x[(long)sn[r] * 64 + (k0 - 448) + kk];
            else               v = g_raw2[(long)sn[r] * 192 + (k0 - 512) + kk];
            As[r][kk] = v;
        }
        for (int idx = tid; idx < 2048; idx += 256) {
            int cc = idx >> 5, kk = idx & 31;
            Bs[kk][cc] = t2w[(long)cc * 704 + k0 + kk];
        }
        __syncthreads();
        #pragma unroll 8
        for (int kk = 0; kk < 32; kk++) {
            float bv = Bs[kk][c];
            #pragma unroll
            for (int r = 0; r < 8; r++) acc[r] = fmaf(As[rg * 8 + r][kk], bv, acc[r]);
        }
        __syncthreads();
    }
    float bias = t2b[c];
    #pragma unroll
    for (int r = 0; r < 8; r++) {
        int row = rows0 + rg * 8 + r;
        float v = lk(acc[r] + bias);
        sv[rg * 8 + r][c] = v;
        if (outok) out[8192 + (long)row * 64 + c] = v;
    }
    __syncthreads();
    int warp = tid >> 5, lane = tid & 31;
    for (int r = warp; r < 32; r += 8) {
        float v0 = sv[r][lane], v1 = sv[r][32 + lane];
        float p0 = v0 * t3w[lane] + v1 * t3w[32 + lane];
        float p1 = v0 * t3w[64 + lane] + v1 * t3w[96 + lane];
        #pragma unroll
        for (int off = 16; off; off >>= 1) {
            p0 += __shfl_down_sync(0xFFFFFFFFu, p0, off);
            p1 += __shfl_down_sync(0xFFFFFFFFu, p1, off);
        }
        if (lane == 0 && outok) {
            out[(rows0 + r) * 2]     = p0 + t3b[0];
            out[(rows0 + r) * 2 + 1] = p1 + t3b[1];
        }
    }
}

// ============================ host launcher ============================
extern "C" void kernel_launch(void* const* d_in, const int* in_sizes, int n_in,
                              void* d_out, int out_size) {
    auto f  = [&](int i) { return (const float*)d_in[i]; };
    auto ip = [&](int i) { return (const int*)d_in[i]; };
    bool dict = (n_in > 1 && in_sizes[1] == Ee);

    const float *h, *t1w, *t1b, *t2w, *t2b, *t3w, *t3b;
    const float *gw1[3], *gb1[3], *hw1[3], *gw2[3], *gb2[3], *hw2[3];
    const int *src[3], *dst[3], *nodes;
    h = f(0);
    if (dict) {
        src[0] = ip(1); dst[0] = ip(2);
        src[1] = ip(3); dst[1] = ip(4);
        src[2] = ip(5); dst[2] = ip(6);
        nodes = ip(7);
        t1w = f(8); t1b = f(9);
        for (int i = 0; i < 3; i++) {
            int b0 = 10 + i * 6;
            gw1[i] = f(b0);     gb1[i] = f(b0 + 1); hw1[i] = f(b0 + 2);
            gw2[i] = f(b0 + 3); gb2[i] = f(b0 + 4); hw2[i] = f(b0 + 5);
        }
        t2w = f(28); t2b = f(29); t3w = f(30); t3b = f(31);
    } else {
        t1w = f(1); t1b = f(2);
        for (int i = 0; i < 3; i++) {
            gw1[i] = f(3 + i * 3);  gb1[i] = f(4 + i * 3);  hw1[i] = f(5 + i * 3);
            gw2[i] = f(12 + i * 3); gb2[i] = f(13 + i * 3); hw2[i] = f(14 + i * 3);
        }
        t2w = f(21); t2b = f(22); t3w = f(23); t3b = f(24);
        src[0] = ip(25); dst[0] = ip(26);
        src[1] = ip(27); dst[1] = ip(28);
        src[2] = ip(29); dst[2] = ip(30);
        nodes = ip(31);
    }
    float* out = (float*)d_out;
    int out_full = (out_size >= Bb * 2 + Bb * 64) ? 1 : 0;

    int t1_smem = (32 * T1_SH_STR + 32 * T1_SW_STR) * 4;
    cudaFuncSetAttribute(k_t1,       cudaFuncAttributeMaxDynamicSharedMemorySize, t1_smem);
    cudaFuncSetAttribute(k_layer1,   cudaFuncAttributeMaxDynamicSharedMemorySize, 24576);
    cudaFuncSetAttribute(k_final_h2, cudaFuncAttributeMaxDynamicSharedMemorySize, 55296);

    k_zero0<<<128, 256>>>();
    k_deg2<<<2048, 256>>>(dst[0], dst[1], dst[2]);
    k_csr<<<3, 1024>>>();
    k_fill<<<2048, 256>>>(src[0], dst[0], src[1], dst[1], src[2], dst[2]);  // #4 -> ncu
    k_t1<<<(Nn + 255) / 256, 256, t1_smem>>>(h, t1w, t1b);
    k_gate1<<<256, 256>>>(gw1[0], gw1[1], gw1[2]);
    dim3 gl1((Nn + 31) / 32, 3);
    k_layer1<<<gl1, 256, 24576>>>(hw1[0], hw1[1], hw1[2], gb1[0], gb1[1], gb1[2]);
    k_gate2<<<256, 256>>>(gw2[0], gw2[1], gw2[2]);
    dim3 gfh(Bb / 8, 3);
    k_final_h2<<<gfh, 256, 55296>>>(nodes, hw2[0], hw2[1], hw2[2],
                                    gb2[0], gb2[1], gb2[2]);
    k_s64<<<Bb / 32, 256>>>(nodes, h, t2w, t2b, t3w, t3b, out, out_full);
}

// round 11
// speedup vs baseline: 1.0915x; 1.0915x over previous
#include <cuda_runtime.h>
#include <math.h>

#define Nn   50000
#define Ee   800000
#define Bb   4096
#define EPSc 0.3f
#define NEGc 0.3f

// ---------------- static device scratch (no allocs allowed) ----------------
__device__ __align__(16) float g_x[Nn * 64];          // raw1 = leaky(h@t1)
__device__ __align__(16) float g_raw2[Nn * 192];      // concat(h1_1..3)
__device__ int    g_deg[3][Nn];
__device__ int    g_off[3][Nn];
__device__ int    g_cur[3][Nn];
__device__ int    g_esrc[3][Ee];
__device__ float  g_d[3][Nn];
__device__ float  g_s1dst[3][Nn];
__device__ float  g_s2dst[3][Nn];
__device__ __align__(8) float2 g_sd1[3][Nn];   // (s1src, d)
__device__ __align__(8) float2 g_sd2[3][Nn];   // (s2src, d)
__device__ __align__(16) float g_final[Bb * 192];  // h2 part only

__device__ __forceinline__ float lk(float x) { return x >= 0.f ? x : NEGc * x; }

// ---- packed f32x2 helpers (FFMA2: only reachable via PTX fma.rn.f32x2) ----
__device__ __forceinline__ void fma2(unsigned long long& d, unsigned long long a,
                                     unsigned long long b) {
    asm("fma.rn.f32x2 %0, %1, %2, %0;" : "+l"(d) : "l"(a), "l"(b));
}
__device__ __forceinline__ unsigned long long pack2(float lo, float hi) {
    unsigned long long r;
    asm("mov.b64 %0, {%1, %2};" : "=l"(r) : "f"(lo), "f"(hi));
    return r;
}
__device__ __forceinline__ void unpack2(unsigned long long v, float& lo, float& hi) {
    asm("mov.b64 {%0, %1}, %2;" : "=f"(lo), "=f"(hi) : "l"(v));
}

// ---------------- zero degree counters ----------------
__global__ void k_zero0() {
    int i = blockIdx.x * blockDim.x + threadIdx.x;
    int stride = gridDim.x * blockDim.x;
    int* dp = &g_deg[0][0];
    for (int j = i; j < 3 * Nn; j += stride) dp[j] = 0;
}

// ---------------- degree count ----------------
__global__ void k_deg2(const int* __restrict__ d1, const int* __restrict__ d2,
                       const int* __restrict__ d3) {
    long i = (long)blockIdx.x * blockDim.x + threadIdx.x;
    long stride = (long)gridDim.x * blockDim.x;
    for (long idx = i; idx < 3L * Ee; idx += stride) {
        int set = (int)(idx / Ee);
        int j = (int)(idx - (long)set * Ee);
        const int* dp = set == 0 ? d1 : set == 1 ? d2 : d3;
        atomicAdd(&g_deg[set][__ldg(dp + j)], 1);
    }
}

// ---------------- CSR offsets (block-wise prefix scan) + dnorm --------------
__global__ void k_csr() {
    int set = blockIdx.x;      // 3 blocks, 1024 threads
    __shared__ int wsum[32];
    __shared__ int carry_s;
    int tid = threadIdx.x;
    int lane = tid & 31, wid = tid >> 5;
    if (tid == 0) carry_s = 0;
    __syncthreads();
    for (int base = 0; base < Nn; base += 1024) {
        int i = base + tid;
        int v = (i < Nn) ? g_deg[set][i] : 0;
        int p = v;
        #pragma unroll
        for (int off = 1; off < 32; off <<= 1) {
            int t = __shfl_up_sync(0xFFFFFFFFu, p, off);
            if (lane >= off) p += t;
        }
        if (lane == 31) wsum[wid] = p;
        __syncthreads();
        if (wid == 0) {
            int s = wsum[lane];
            #pragma unroll
            for (int off = 1; off < 32; off <<= 1) {
                int t = __shfl_up_sync(0xFFFFFFFFu, s, off);
                if (lane >= off) s += t;
            }
            wsum[lane] = s;
        }
        __syncthreads();
        int woff = wid ? wsum[wid - 1] : 0;
        int excl = carry_s + woff + p - v;
        if (i < Nn) {
            g_off[set][i] = excl;
            g_cur[set][i] = excl;
            g_d[set][i] = v > 0 ? rsqrtf((float)v) : 0.f;
        }
        __syncthreads();
        if (tid == 0) carry_s += wsum[31];
        __syncthreads();
    }
}

// ---------------- CSR fill: scatter src ids by dst ----------------
__global__ void k_fill(const int* __restrict__ s1, const int* __restrict__ d1,
                       const int* __restrict__ s2, const int* __restrict__ d2,
                       const int* __restrict__ s3, const int* __restrict__ d3) {
    long i = (long)blockIdx.x * blockDim.x + threadIdx.x;
    long stride = (long)gridDim.x * blockDim.x;
    for (long idx = i; idx < 3L * Ee; idx += stride) {
        int set = (int)(idx / Ee);
        int j = (int)(idx - (long)set * Ee);
        const int* sp = set == 0 ? s1 : set == 1 ? s2 : s3;
        const int* dp = set == 0 ? d1 : set == 1 ? d2 : d3;
        int s = __ldg(sp + j);
        int dd = __ldg(dp + j);
        int pos = atomicAdd(&g_cur[set][dd], 1);
        g_esrc[set][pos] = s;
    }
}

// ---------------- t1: x = leaky(h @ t1_w^T + b) — f32x2-packed tiling -------
// (R9 variant, measured 55.5us: 128 nodes x 64 outs, thread = 4 node-pairs x 4 outs)
#define SH_STR 136
#define SW_STR 68
__global__ void __launch_bounds__(256, 3)
k_t1(const float* __restrict__ h, const float* __restrict__ w,
     const float* __restrict__ bias) {
    extern __shared__ float sm[];
    float* sh = sm;                 // [32][SH_STR]  sh[k][node]
    float* sW = sm + 32 * SH_STR;   // [32][SW_STR]  sW[k][o]
    int tid = threadIdx.x;
    int tx = tid & 15, ty = tid >> 4;   // tx: out group (4), ty: node group (8)
    int ob = tx * 4;
    int nb = blockIdx.x * 128;
    unsigned long long acc[4][4];       // [nodepair][out]
    float4 bv = *(const float4*)(bias + ob);
    {
        unsigned long long b0 = pack2(bv.x, bv.x), b1 = pack2(bv.y, bv.y);
        unsigned long long b2 = pack2(bv.z, bv.z), b3 = pack2(bv.w, bv.w);
        #pragma unroll
        for (int j = 0; j < 4; j++) {
            acc[j][0] = b0; acc[j][1] = b1; acc[j][2] = b2; acc[j][3] = b3;
        }
    }
    int nrow = tid >> 3;            // 0..31
    int kq = (tid & 7) * 4;         // 0,4,..,28
    for (int k0 = 0; k0 < 256; k0 += 32) {
        __syncthreads();
        // load h chunk transposed: sh[k][n_local]
        #pragma unroll
        for (int p = 0; p < 4; p++) {
            int nl = p * 32 + nrow;
            int n = nb + nl;
            float4 hv = make_float4(0.f, 0.f, 0.f, 0.f);
            if (n < Nn) hv = *(const float4*)(h + (long)n * 256 + k0 + kq);
            sh[(kq + 0) * SH_STR + nl] = hv.x;
            sh[(kq + 1) * SH_STR + nl] = hv.y;
            sh[(kq + 2) * SH_STR + nl] = hv.z;
            sh[(kq + 3) * SH_STR + nl] = hv.w;
        }
        // load W chunk transposed: sW[k][o]   (w is [64][256] row-major)
        {
            int o = tid >> 2;           // 0..63
            int kk = (tid & 3) * 8;     // 0,8,16,24
            float4 wa = *(const float4*)(w + (long)o * 256 + k0 + kk);
            float4 wb = *(const float4*)(w + (long)o * 256 + k0 + kk + 4);
            sW[(kk + 0) * SW_STR + o] = wa.x;
            sW[(kk + 1) * SW_STR + o] = wa.y;
            sW[(kk + 2) * SW_STR + o] = wa.z;
            sW[(kk + 3) * SW_STR + o] = wa.w;
            sW[(kk + 4) * SW_STR + o] = wb.x;
            sW[(kk + 5) * SW_STR + o] = wb.y;
            sW[(kk + 6) * SW_STR + o] = wb.z;
            sW[(kk + 7) * SW_STR + o] = wb.w;
        }
        __syncthreads();
        #pragma unroll 8
        for (int k = 0; k < 32; k++) {
            float4 wv = *(const float4*)(sW + k * SW_STR + ob);
            const ulonglong2* hp = (const ulonglong2*)(sh + k * SH_STR + ty * 8);
            ulonglong2 hA = hp[0], hB = hp[1];   // 2x LDS.128
            unsigned long long w0 = pack2(wv.x, wv.x), w1 = pack2(wv.y, wv.y);
            unsigned long long w2 = pack2(wv.z, wv.z), w3 = pack2(wv.w, wv.w);
            fma2(acc[0][0], hA.x, w0); fma2(acc[0][1], hA.x, w1);
            fma2(acc[0][2], hA.x, w2); fma2(acc[0][3], hA.x, w3);
            fma2(acc[1][0], hA.y, w0); fma2(acc[1][1], hA.y, w1);
            fma2(acc[1][2], hA.y, w2); fma2(acc[1][3], hA.y, w3);
            fma2(acc[2][0], hB.x, w0); fma2(acc[2][1], hB.x, w1);
            fma2(acc[2][2], hB.x, w2); fma2(acc[2][3], hB.x, w3);
            fma2(acc[3][0], hB.y, w0); fma2(acc[3][1], hB.y, w1);
            fma2(acc[3][2], hB.y, w2); fma2(acc[3][3], hB.y, w3);
        }
    }
    #pragma unroll
    for (int j = 0; j < 4; j++) {
        float lo0, hi0, lo1, hi1, lo2, hi2, lo3, hi3;
        unpack2(acc[j][0], lo0, hi0); unpack2(acc[j][1], lo1, hi1);
        unpack2(acc[j][2], lo2, hi2); unpack2(acc[j][3], lo3, hi3);
        int n0 = nb + ty * 8 + j * 2;
        if (n0 < Nn) {
            float4 r; r.x = lk(lo0); r.y = lk(lo1); r.z = lk(lo2); r.w = lk(lo3);
            *(float4*)(g_x + (long)n0 * 64 + ob) = r;
        }
        if (n0 + 1 < Nn) {
            float4 r; r.x = lk(hi0); r.y = lk(hi1); r.z = lk(hi2); r.w = lk(hi3);
            *(float4*)(g_x + (long)(n0 + 1) * 64 + ob) = r;
        }
    }
}

// ---------------- per-node gate scalars, layer 1 (D=64) ----------------
__global__ void k_gate1(const float* __restrict__ w0, const float* __restrict__ w1,
                        const float* __restrict__ w2) {
    int gt = blockIdx.x * blockDim.x + threadIdx.x;
    int warp = gt >> 5, lane = gt & 31;
    int nw = (gridDim.x * blockDim.x) >> 5;
    for (int n = warp; n < Nn; n += nw) {
        float x0 = g_x[n * 64 + lane];
        float x1 = g_x[n * 64 + 32 + lane];
        #pragma unroll
        for (int g = 0; g < 3; g++) {
            const float* w = g == 0 ? w0 : g == 1 ? w1 : w2;
            float pd = x0 * w[lane] + x1 * w[32 + lane];
            float ps = x0 * w[64 + lane] + x1 * w[96 + lane];
            #pragma unroll
            for (int off = 16; off; off >>= 1) {
                pd += __shfl_down_sync(0xFFFFFFFFu, pd, off);
                ps += __shfl_down_sync(0xFFFFFFFFu, ps, off);
            }
            if (lane == 0) {
                g_s1dst[g][n] = pd;
                g_sd1[g][n] = make_float2(ps, g_d[g][n]);
            }
        }
    }
}

// ------ fused layer-1: CSR gather-aggregate + hw1 transform -> raw2 ---------
// (R9 variant: 4-wide MLP gather loop)
__global__ void __launch_bounds__(256)
k_layer1(const float* __restrict__ hw0, const float* __restrict__ hw1p,
         const float* __restrict__ hw2p, const float* __restrict__ b1,
         const float* __restrict__ b2, const float* __restrict__ b3) {
    extern __shared__ float sm[];
    float* sW = sm;          // [64][64]
    float* su = sm + 4096;   // [8 warps][4][64]
    int set = blockIdx.y;
    const float* w = set == 0 ? hw0 : set == 1 ? hw1p : hw2p;
    float gb = (set == 0 ? b1 : set == 1 ? b2 : b3)[0];
    int tid = threadIdx.x;
    for (int idx = tid; idx < 4096; idx += 256) sW[idx] = w[idx];
    __syncthreads();
    int warp = tid >> 5, lane = tid & 31;
    int nb = blockIdx.x * 32 + warp * 4;
    const float2* x2 = (const float2*)g_x;
    float2 acc[4];
    #pragma unroll
    for (int j = 0; j < 4; j++) { acc[j].x = 0.f; acc[j].y = 0.f; }
    #pragma unroll
    for (int j = 0; j < 4; j++) {
        int n = nb + j;
        if (n >= Nn) continue;
        int deg = g_deg[set][n];
        int off = g_off[set][n];
        float sd = g_s1dst[set][n] + gb;
        float ddn = g_d[set][n];
        for (int base = 0; base < deg; base += 32) {
            int jj = base + lane;
            int src = 0;
            float e = 0.f;
            if (jj < deg) {
                src = __ldg(&g_esrc[set][off + jj]);
                float2 sv = g_sd1[set][src];
                e = tanhf(sd + sv.x) * ddn * sv.y;
            }
            int m = min(32, deg - base);
            int t = 0;
            for (; t + 4 <= m; t += 4) {
                int s0 = __shfl_sync(0xFFFFFFFFu, src, t);
                int s1v = __shfl_sync(0xFFFFFFFFu, src, t + 1);
                int s2v = __shfl_sync(0xFFFFFFFFu, src, t + 2);
                int s3v = __shfl_sync(0xFFFFFFFFu, src, t + 3);
                float e0 = __shfl_sync(0xFFFFFFFFu, e, t);
                float e1 = __shfl_sync(0xFFFFFFFFu, e, t + 1);
                float e2 = __shfl_sync(0xFFFFFFFFu, e, t + 2);
                float e3 = __shfl_sync(0xFFFFFFFFu, e, t + 3);
                float2 v0 = x2[(long)s0 * 32 + lane];
                float2 v1 = x2[(long)s1v * 32 + lane];
                float2 v2 = x2[(long)s2v * 32 + lane];
                float2 v3 = x2[(long)s3v * 32 + lane];
                acc[j].x = fmaf(e0, v0.x, acc[j].x);
                acc[j].y = fmaf(e0, v0.y, acc[j].y);
                acc[j].x = fmaf(e1, v1.x, acc[j].x);
                acc[j].y = fmaf(e1, v1.y, acc[j].y);
                acc[j].x = fmaf(e2, v2.x, acc[j].x);
                acc[j].y = fmaf(e2, v2.y, acc[j].y);
                acc[j].x = fmaf(e3, v3.x, acc[j].x);
                acc[j].y = fmaf(e3, v3.y, acc[j].y);
            }
            for (; t < m; t++) {
                float ee = __shfl_sync(0xFFFFFFFFu, e, t);
                int sj = __shfl_sync(0xFFFFFFFFu, src, t);
                float2 v = x2[(long)sj * 32 + lane];
                acc[j].x = fmaf(ee, v.x, acc[j].x);
                acc[j].y = fmaf(ee, v.y, acc[j].y);
            }
        }
    }
    float* myu = su + warp * 256;
    #pragma unroll
    for (int j = 0; j < 4; j++) {
        int n = nb + j;
        float2 xv = make_float2(0.f, 0.f);
        if (n < Nn) xv = x2[(long)n * 32 + lane];
        myu[j * 64 + 2 * lane]     = EPSc * xv.x + acc[j].x;
        myu[j * 64 + 2 * lane + 1] = EPSc * xv.y + acc[j].y;
    }
    __syncwarp();
    float o[4][2] = {};
    #pragma unroll 8
    for (int k = 0; k < 64; k++) {
        float w0 = sW[k * 64 + lane], w1 = sW[k * 64 + 32 + lane];
        #pragma unroll
        for (int j = 0; j < 4; j++) {
            float uk = myu[j * 64 + k];
            o[j][0] = fmaf(uk, w0, o[j][0]);
            o[j][1] = fmaf(uk, w1, o[j][1]);
        }
    }
    #pragma unroll
    for (int j = 0; j < 4; j++) {
        int n = nb + j;
        if (n < Nn) {
            g_raw2[(long)n * 192 + set * 64 + lane]      = lk(o[j][0]);
            g_raw2[(long)n * 192 + set * 64 + 32 + lane] = lk(o[j][1]);
        }
    }
}

// ---------------- per-node gate scalars, layer 2 (D=192) ----------------
__global__ void k_gate2(const float* __restrict__ w0, const float* __restrict__ w1,
                        const float* __restrict__ w2) {
    int gt = blockIdx.x * blockDim.x + threadIdx.x;
    int warp = gt >> 5, lane = gt & 31;
    int nw = (gridDim.x * blockDim.x) >> 5;
    for (int n = warp; n < Nn; n += nw) {
        float r[6];
        #pragma unroll
        for (int t = 0; t < 6; t++) r[t] = g_raw2[(long)n * 192 + lane + 32 * t];
        #pragma unroll
        for (int g = 0; g < 3; g++) {
            const float* w = g == 0 ? w0 : g == 1 ? w1 : w2;
            float pd = 0.f, ps = 0.f;
            #pragma unroll
            for (int t = 0; t < 6; t++) {
                pd = fmaf(r[t], w[lane + 32 * t], pd);
                ps = fmaf(r[t], w[192 + lane + 32 * t], ps);
            }
            #pragma unroll
            for (int off = 16; off; off >>= 1) {
                pd += __shfl_down_sync(0xFFFFFFFFu, pd, off);
                ps += __shfl_down_sync(0xFFFFFFFFu, ps, off);
            }
            if (lane == 0) {
                g_s2dst[g][n] = pd;
                g_sd2[g][n] = make_float2(ps, g_d[g][n]);
            }
        }
    }
}

// ------ fused layer-2 for SELECTED nodes: CSR gather + hw2 -> final[:,0:192] -
__global__ void k_final_h2(const int* __restrict__ nodes,
                           const float* __restrict__ hw0, const float* __restrict__ hw1p,
                           const float* __restrict__ hw2p, const float* __restrict__ b1,
                           const float* __restrict__ b2, const float* __restrict__ b3) {
    extern __shared__ float sm[];
    float* sW = sm;             // [192][64]
    float* su = sm + 12288;     // [8][192]
    int i = blockIdx.y;
    const float* w = i == 0 ? hw0 : i == 1 ? hw1p : hw2p;
    float gb = (i == 0 ? b1 : i == 1 ? b2 : b3)[0];
    int tid = threadIdx.x;
    for (int idx = tid; idx < 12288; idx += 256) sW[idx] = w[idx];
    __syncthreads();
    int warp = tid >> 5, lane = tid & 31;
    int b = blockIdx.x * 8 + warp;
    int n = nodes[b];
    int deg = g_deg[i][n], off = g_off[i][n];
    float sd = g_s2dst[i][n] + gb;
    float ddn = g_d[i][n];
    float acc[6] = {};
    for (int base = 0; base < deg; base += 32) {
        int jj = base + lane;
        int src = 0;
        float e = 0.f;
        if (jj < deg) {
            src = __ldg(&g_esrc[i][off + jj]);
            float2 sv = g_sd2[i][src];
            e = tanhf(sd + sv.x) * ddn * sv.y;
        }
        int m = min(32, deg - base);
        for (int t = 0; t < m; t++) {
            float ee = __shfl_sync(0xFFFFFFFFu, e, t);
            int sj = __shfl_sync(0xFFFFFFFFu, src, t);
            const float* rp = g_raw2 + (long)sj * 192 + lane;
            #pragma unroll
            for (int q = 0; q < 6; q++)
                acc[q] = fmaf(ee, rp[q * 32], acc[q]);
        }
    }
    #pragma unroll
    for (int q = 0; q < 6; q++) {
        int k = lane + 32 * q;
        su[warp * 192 + k] = EPSc * g_raw2[(long)n * 192 + k] + acc[q];
    }
    __syncwarp();
    float a0 = 0.f, a1 = 0.f;
    #pragma unroll 8
    for (int k = 0; k < 192; k++) {
        float uk = su[warp * 192 + k];
        a0 = fmaf(uk, sW[k * 64 + lane], a0);
        a1 = fmaf(uk, sW[k * 64 + 32 + lane], a1);
    }
    g_final[(long)b * 192 + i * 64 + lane] = lk(a0);
    g_final[(long)b * 192 + i * 64 + 32 + lane] = lk(a1);
}

// ------ s64 = leaky(final @ t2_w^T + b) + fused scores, fused column gather --
__global__ void k_s64(const int* __restrict__ nodes, const float* __restrict__ h,
                      const float* __restrict__ t2w, const float* __restrict__ t2b,
                      const float* __restrict__ t3w, const float* __restrict__ t3b,
                      float* __restrict__ out, int outok) {
    __shared__ float As[32][32];
    __shared__ float Bs[32][65];
    __shared__ float sv[32][65];
    __shared__ int sn[32];
    int tid = threadIdx.x;
    int c = tid & 63, rg = tid >> 6;
    int rows0 = blockIdx.x * 32;
    if (tid < 32) sn[tid] = nodes[rows0 + tid];
    __syncthreads();
    float acc[8];
    #pragma unroll
    for (int r = 0; r < 8; r++) acc[r] = 0.f;
    for (int k0 = 0; k0 < 704; k0 += 32) {
        for (int idx = tid; idx < 1024; idx += 256) {
            int r = idx >> 5, kk = idx & 31;
            float v;
            if (k0 < 192)      v = g_final[(long)(rows0 + r) * 192 + k0 + kk];
            else if (k0 < 448) v = h[(long)sn[r] * 256 + (k0 - 192) + kk];
            else if (k0 < 512) v = g_x[(long)sn[r] * 64 + (k0 - 448) + kk];
            else               v = g_raw2[(long)sn[r] * 192 + (k0 - 512) + kk];
            As[r][kk] = v;
        }
        for (int idx = tid; idx < 2048; idx += 256) {
            int cc = idx >> 5, kk = idx & 31;
            Bs[kk][cc] = t2w[(long)cc * 704 + k0 + kk];
        }
        __syncthreads();
        #pragma unroll 8
        for (int kk = 0; kk < 32; kk++) {
            float bv = Bs[kk][c];
            #pragma unroll
            for (int r = 0; r < 8; r++) acc[r] = fmaf(As[rg * 8 + r][kk], bv, acc[r]);
        }
        __syncthreads();
    }
    float bias = t2b[c];
    #pragma unroll
    for (int r = 0; r < 8; r++) {
        int row = rows0 + rg * 8 + r;
        float v = lk(acc[r] + bias);
        sv[rg * 8 + r][c] = v;
        if (outok) out[8192 + (long)row * 64 + c] = v;
    }
    __syncthreads();
    int warp = tid >> 5, lane = tid & 31;
    for (int r = warp; r < 32; r += 8) {
        float v0 = sv[r][lane], v1 = sv[r][32 + lane];
        float p0 = v0 * t3w[lane] + v1 * t3w[32 + lane];
        float p1 = v0 * t3w[64 + lane] + v1 * t3w[96 + lane];
        #pragma unroll
        for (int off = 16; off; off >>= 1) {
            p0 += __shfl_down_sync(0xFFFFFFFFu, p0, off);
            p1 += __shfl_down_sync(0xFFFFFFFFu, p1, off);
        }
        if (lane == 0 && outok) {
            out[(rows0 + r) * 2]     = p0 + t3b[0];
            out[(rows0 + r) * 2 + 1] = p1 + t3b[1];
        }
    }
}

// ============================ host launcher ============================
extern "C" void kernel_launch(void* const* d_in, const int* in_sizes, int n_in,
                              void* d_out, int out_size) {
    auto f  = [&](int i) { return (const float*)d_in[i]; };
    auto ip = [&](int i) { return (const int*)d_in[i]; };
    bool dict = (n_in > 1 && in_sizes[1] == Ee);

    const float *h, *t1w, *t1b, *t2w, *t2b, *t3w, *t3b;
    const float *gw1[3], *gb1[3], *hw1[3], *gw2[3], *gb2[3], *hw2[3];
    const int *src[3], *dst[3], *nodes;
    h = f(0);
    if (dict) {
        src[0] = ip(1); dst[0] = ip(2);
        src[1] = ip(3); dst[1] = ip(4);
        src[2] = ip(5); dst[2] = ip(6);
        nodes = ip(7);
        t1w = f(8); t1b = f(9);
        for (int i = 0; i < 3; i++) {
            int b0 = 10 + i * 6;
            gw1[i] = f(b0);     gb1[i] = f(b0 + 1); hw1[i] = f(b0 + 2);
            gw2[i] = f(b0 + 3); gb2[i] = f(b0 + 4); hw2[i] = f(b0 + 5);
        }
        t2w = f(28); t2b = f(29); t3w = f(30); t3b = f(31);
    } else {
        t1w = f(1); t1b = f(2);
        for (int i = 0; i < 3; i++) {
            gw1[i] = f(3 + i * 3);  gb1[i] = f(4 + i * 3);  hw1[i] = f(5 + i * 3);
            gw2[i] = f(12 + i * 3); gb2[i] = f(13 + i * 3); hw2[i] = f(14 + i * 3);
        }
        t2w = f(21); t2b = f(22); t3w = f(23); t3b = f(24);
        src[0] = ip(25); dst[0] = ip(26);
        src[1] = ip(27); dst[1] = ip(28);
        src[2] = ip(29); dst[2] = ip(30);
        nodes = ip(31);
    }
    float* out = (float*)d_out;
    int out_full = (out_size >= Bb * 2 + Bb * 64) ? 1 : 0;

    int t1_smem = (32 * SH_STR + 32 * SW_STR) * 4;
    cudaFuncSetAttribute(k_t1,       cudaFuncAttributeMaxDynamicSharedMemorySize, t1_smem);
    cudaFuncSetAttribute(k_layer1,   cudaFuncAttributeMaxDynamicSharedMemorySize, 24576);
    cudaFuncSetAttribute(k_final_h2, cudaFuncAttributeMaxDynamicSharedMemorySize, 55296);

    k_zero0<<<128, 256>>>();
    k_deg2<<<2048, 256>>>(dst[0], dst[1], dst[2]);
    k_csr<<<3, 1024>>>();
    k_fill<<<2048, 256>>>(src[0], dst[0], src[1], dst[1], src[2], dst[2]);
    k_t1<<<(Nn + 127) / 128, 256, t1_smem>>>(h, t1w, t1b);
    k_gate1<<<256, 256>>>(gw1[0], gw1[1], gw1[2]);
    dim3 gl1((Nn + 31) / 32, 3);
    k_layer1<<<gl1, 256, 24576>>>(hw1[0], hw1[1], hw1[2], gb1[0], gb1[1], gb1[2]);
    k_gate2<<<256, 256>>>(gw2[0], gw2[1], gw2[2]);
    dim3 gfh(Bb / 8, 3);
    k_final_h2<<<gfh, 256, 55296>>>(nodes, hw2[0], hw2[1], hw2[2],
                                    gb2[0], gb2[1], gb2[2]);
    k_s64<<<Bb / 32, 256>>>(nodes, h, t2w, t2b, t3w, t3b, out, out_full);
}

// round 15
// speedup vs baseline: 1.2289x; 1.1259x over previous
#include <cuda_runtime.h>
#include <math.h>

#define Nn     50000
#define Ee     800000
#define Bb     4096
#define EPSc   0.3f
#define NEGc   0.3f
#define MAXDEG 128

// ---------------- static device scratch (no allocs allowed) ----------------
// NOTE: g_deg relies on zero-init at module load + re-zeroing by k_ztail at the
// end of every run, so each kernel_launch (and each graph replay) starts clean.
__device__ __align__(16) float g_x[Nn * 64];          // raw1 = leaky(h@t1)
__device__ __align__(16) float g_raw2[Nn * 192];      // concat(h1_1..3)
__device__ int    g_deg[3][Nn];
__device__ int    g_esrc[3][Nn * MAXDEG];             // padded per-dst buckets
__device__ float  g_d[3][Nn];
__device__ float  g_s1dst[3][Nn];
__device__ float  g_s2dst[3][Nn];
__device__ __align__(8) float2 g_sd1[3][Nn];   // (s1src, d)
__device__ __align__(8) float2 g_sd2[3][Nn];   // (s2src, d)
__device__ __align__(16) float g_final[Bb * 192];  // h2 part only

__device__ __forceinline__ float lk(float x) { return x >= 0.f ? x : NEGc * x; }

// ---- packed f32x2 helpers (FFMA2: only reachable via PTX fma.rn.f32x2) ----
__device__ __forceinline__ void fma2(unsigned long long& d, unsigned long long a,
                                     unsigned long long b) {
    asm("fma.rn.f32x2 %0, %1, %2, %0;" : "+l"(d) : "l"(a), "l"(b));
}
__device__ __forceinline__ unsigned long long pack2(float lo, float hi) {
    unsigned long long r;
    asm("mov.b64 %0, {%1, %2};" : "=l"(r) : "f"(lo), "f"(hi));
    return r;
}
__device__ __forceinline__ void unpack2(unsigned long long v, float& lo, float& hi) {
    asm("mov.b64 {%0, %1}, %2;" : "=f"(lo), "=f"(hi) : "l"(v));
}

// ------ one-pass padded bucket fill: count degree + place src id -----------
__global__ void k_fillpad(const int* __restrict__ s1, const int* __restrict__ d1,
                          const int* __restrict__ s2, const int* __restrict__ d2,
                          const int* __restrict__ s3, const int* __restrict__ d3) {
    long i = (long)blockIdx.x * blockDim.x + threadIdx.x;
    long stride = (long)gridDim.x * blockDim.x;
    for (long idx = i; idx < 3L * Ee; idx += stride) {
        int set = (int)(idx / Ee);
        int j = (int)(idx - (long)set * Ee);
        const int* sp = set == 0 ? s1 : set == 1 ? s2 : s3;
        const int* dp = set == 0 ? d1 : set == 1 ? d2 : d3;
        int s = __ldg(sp + j);
        int dd = __ldg(dp + j);
        int pos = atomicAdd(&g_deg[set][dd], 1);
        if (pos < MAXDEG) g_esrc[set][dd * MAXDEG + pos] = s;
    }
}

// ---------------- t1: x = leaky(h @ t1_w^T + b) — f32x2-packed tiling -------
#define SH_STR 136
#define SW_STR 68
__global__ void __launch_bounds__(256, 3)
k_t1(const float* __restrict__ h, const float* __restrict__ w,
     const float* __restrict__ bias) {
    extern __shared__ float sm[];
    float* sh = sm;                 // [32][SH_STR]  sh[k][node]
    float* sW = sm + 32 * SH_STR;   // [32][SW_STR]  sW[k][o]
    int tid = threadIdx.x;
    int tx = tid & 15, ty = tid >> 4;
    int ob = tx * 4;
    int nb = blockIdx.x * 128;
    unsigned long long acc[4][4];
    float4 bv = *(const float4*)(bias + ob);
    {
        unsigned long long b0 = pack2(bv.x, bv.x), b1 = pack2(bv.y, bv.y);
        unsigned long long b2 = pack2(bv.z, bv.z), b3 = pack2(bv.w, bv.w);
        #pragma unroll
        for (int j = 0; j < 4; j++) {
            acc[j][0] = b0; acc[j][1] = b1; acc[j][2] = b2; acc[j][3] = b3;
        }
    }
    int nrow = tid >> 3;
    int kq = (tid & 7) * 4;
    for (int k0 = 0; k0 < 256; k0 += 32) {
        __syncthreads();
        #pragma unroll
        for (int p = 0; p < 4; p++) {
            int nl = p * 32 + nrow;
            int n = nb + nl;
            float4 hv = make_float4(0.f, 0.f, 0.f, 0.f);
            if (n < Nn) hv = *(const float4*)(h + (long)n * 256 + k0 + kq);
            sh[(kq + 0) * SH_STR + nl] = hv.x;
            sh[(kq + 1) * SH_STR + nl] = hv.y;
            sh[(kq + 2) * SH_STR + nl] = hv.z;
            sh[(kq + 3) * SH_STR + nl] = hv.w;
        }
        {
            int o = tid >> 2;
            int kk = (tid & 3) * 8;
            float4 wa = *(const float4*)(w + (long)o * 256 + k0 + kk);
            float4 wb = *(const float4*)(w + (long)o * 256 + k0 + kk + 4);
            sW[(kk + 0) * SW_STR + o] = wa.x;
            sW[(kk + 1) * SW_STR + o] = wa.y;
            sW[(kk + 2) * SW_STR + o] = wa.z;
            sW[(kk + 3) * SW_STR + o] = wa.w;
            sW[(kk + 4) * SW_STR + o] = wb.x;
            sW[(kk + 5) * SW_STR + o] = wb.y;
            sW[(kk + 6) * SW_STR + o] = wb.z;
            sW[(kk + 7) * SW_STR + o] = wb.w;
        }
        __syncthreads();
        #pragma unroll 8
        for (int k = 0; k < 32; k++) {
            float4 wv = *(const float4*)(sW + k * SW_STR + ob);
            const ulonglong2* hp = (const ulonglong2*)(sh + k * SH_STR + ty * 8);
            ulonglong2 hA = hp[0], hB = hp[1];
            unsigned long long w0 = pack2(wv.x, wv.x), w1 = pack2(wv.y, wv.y);
            unsigned long long w2 = pack2(wv.z, wv.z), w3 = pack2(wv.w, wv.w);
            fma2(acc[0][0], hA.x, w0); fma2(acc[0][1], hA.x, w1);
            fma2(acc[0][2], hA.x, w2); fma2(acc[0][3], hA.x, w3);
            fma2(acc[1][0], hA.y, w0); fma2(acc[1][1], hA.y, w1);
            fma2(acc[1][2], hA.y, w2); fma2(acc[1][3], hA.y, w3);
            fma2(acc[2][0], hB.x, w0); fma2(acc[2][1], hB.x, w1);
            fma2(acc[2][2], hB.x, w2); fma2(acc[2][3], hB.x, w3);
            fma2(acc[3][0], hB.y, w0); fma2(acc[3][1], hB.y, w1);
            fma2(acc[3][2], hB.y, w2); fma2(acc[3][3], hB.y, w3);
        }
    }
    #pragma unroll
    for (int j = 0; j < 4; j++) {
        float lo0, hi0, lo1, hi1, lo2, hi2, lo3, hi3;
        unpack2(acc[j][0], lo0, hi0); unpack2(acc[j][1], lo1, hi1);
        unpack2(acc[j][2], lo2, hi2); unpack2(acc[j][3], lo3, hi3);
        int n0 = nb + ty * 8 + j * 2;
        if (n0 < Nn) {
            float4 r; r.x = lk(lo0); r.y = lk(lo1); r.z = lk(lo2); r.w = lk(lo3);
            *(float4*)(g_x + (long)n0 * 64 + ob) = r;
        }
        if (n0 + 1 < Nn) {
            float4 r; r.x = lk(hi0); r.y = lk(hi1); r.z = lk(hi2); r.w = lk(hi3);
            *(float4*)(g_x + (long)(n0 + 1) * 64 + ob) = r;
        }
    }
}

// ------- gate scalars layer 1 (D=64) + on-the-fly degree norm --------------
__global__ void k_gate1(const float* __restrict__ w0, const float* __restrict__ w1,
                        const float* __restrict__ w2) {
    int gt = blockIdx.x * blockDim.x + threadIdx.x;
    int warp = gt >> 5, lane = gt & 31;
    int nw = (gridDim.x * blockDim.x) >> 5;
    for (int n = warp; n < Nn; n += nw) {
        float x0 = g_x[n * 64 + lane];
        float x1 = g_x[n * 64 + 32 + lane];
        #pragma unroll
        for (int g = 0; g < 3; g++) {
            const float* w = g == 0 ? w0 : g == 1 ? w1 : w2;
            float pd = x0 * w[lane] + x1 * w[32 + lane];
            float ps = x0 * w[64 + lane] + x1 * w[96 + lane];
            #pragma unroll
            for (int off = 16; off; off >>= 1) {
                pd += __shfl_down_sync(0xFFFFFFFFu, pd, off);
                ps += __shfl_down_sync(0xFFFFFFFFu, ps, off);
            }
            if (lane == 0) {
                int dg = g_deg[g][n];
                float d = dg > 0 ? rsqrtf((float)dg) : 0.f;
                g_d[g][n] = d;
                g_s1dst[g][n] = pd;
                g_sd1[g][n] = make_float2(ps, d);
            }
        }
    }
}

// ------ fused layer-1: bucket gather-aggregate + hw1 transform -> raw2 ------
__global__ void __launch_bounds__(256)
k_layer1(const float* __restrict__ hw0, const float* __restrict__ hw1p,
         const float* __restrict__ hw2p, const float* __restrict__ b1,
         const float* __restrict__ b2, const float* __restrict__ b3) {
    extern __shared__ float sm[];
    float* sW = sm;          // [64][64]
    float* su = sm + 4096;   // [8 warps][4][64]
    int set = blockIdx.y;
    const float* w = set == 0 ? hw0 : set == 1 ? hw1p : hw2p;
    float gb = (set == 0 ? b1 : set == 1 ? b2 : b3)[0];
    int tid = threadIdx.x;
    for (int idx = tid; idx < 4096; idx += 256) sW[idx] = w[idx];
    __syncthreads();
    int warp = tid >> 5, lane = tid & 31;
    int nb = blockIdx.x * 32 + warp * 4;
    const float2* x2 = (const float2*)g_x;
    float2 acc[4];
    #pragma unroll
    for (int j = 0; j < 4; j++) { acc[j].x = 0.f; acc[j].y = 0.f; }
    #pragma unroll
    for (int j = 0; j < 4; j++) {
        int n = nb + j;
        if (n >= Nn) continue;
        int deg = min(g_deg[set][n], MAXDEG);
        int off = n * MAXDEG;
        float sd = g_s1dst[set][n] + gb;
        float ddn = g_d[set][n];
        for (int base = 0; base < deg; base += 32) {
            int jj = base + lane;
            int src = 0;
            float e = 0.f;
            if (jj < deg) {
                src = __ldg(&g_esrc[set][off + jj]);
                float2 sv = g_sd1[set][src];
                e = tanhf(sd + sv.x) * ddn * sv.y;
            }
            int m = min(32, deg - base);
            int t = 0;
            for (; t + 4 <= m; t += 4) {
                int s0 = __shfl_sync(0xFFFFFFFFu, src, t);
                int s1v = __shfl_sync(0xFFFFFFFFu, src, t + 1);
                int s2v = __shfl_sync(0xFFFFFFFFu, src, t + 2);
                int s3v = __shfl_sync(0xFFFFFFFFu, src, t + 3);
                float e0 = __shfl_sync(0xFFFFFFFFu, e, t);
                float e1 = __shfl_sync(0xFFFFFFFFu, e, t + 1);
                float e2 = __shfl_sync(0xFFFFFFFFu, e, t + 2);
                float e3 = __shfl_sync(0xFFFFFFFFu, e, t + 3);
                float2 v0 = x2[(long)s0 * 32 + lane];
                float2 v1 = x2[(long)s1v * 32 + lane];
                float2 v2 = x2[(long)s2v * 32 + lane];
                float2 v3 = x2[(long)s3v * 32 + lane];
                acc[j].x = fmaf(e0, v0.x, acc[j].x);
                acc[j].y = fmaf(e0, v0.y, acc[j].y);
                acc[j].x = fmaf(e1, v1.x, acc[j].x);
                acc[j].y = fmaf(e1, v1.y, acc[j].y);
                acc[j].x = fmaf(e2, v2.x, acc[j].x);
                acc[j].y = fmaf(e2, v2.y, acc[j].y);
                acc[j].x = fmaf(e3, v3.x, acc[j].x);
                acc[j].y = fmaf(e3, v3.y, acc[j].y);
            }
            for (; t < m; t++) {
                float ee = __shfl_sync(0xFFFFFFFFu, e, t);
                int sj = __shfl_sync(0xFFFFFFFFu, src, t);
                float2 v = x2[(long)sj * 32 + lane];
                acc[j].x = fmaf(ee, v.x, acc[j].x);
                acc[j].y = fmaf(ee, v.y, acc[j].y);
            }
        }
    }
    float* myu = su + warp * 256;
    #pragma unroll
    for (int j = 0; j < 4; j++) {
        int n = nb + j;
        float2 xv = make_float2(0.f, 0.f);
        if (n < Nn) xv = x2[(long)n * 32 + lane];
        myu[j * 64 + 2 * lane]     = EPSc * xv.x + acc[j].x;
        myu[j * 64 + 2 * lane + 1] = EPSc * xv.y + acc[j].y;
    }
    __syncwarp();
    float o[4][2] = {};
    #pragma unroll 8
    for (int k = 0; k < 64; k++) {
        float w0 = sW[k * 64 + lane], w1 = sW[k * 64 + 32 + lane];
        #pragma unroll
        for (int j = 0; j < 4; j++) {
            float uk = myu[j * 64 + k];
            o[j][0] = fmaf(uk, w0, o[j][0]);
            o[j][1] = fmaf(uk, w1, o[j][1]);
        }
    }
    #pragma unroll
    for (int j = 0; j < 4; j++) {
        int n = nb + j;
        if (n < Nn) {
            g_raw2[(long)n * 192 + set * 64 + lane]      = lk(o[j][0]);
            g_raw2[(long)n * 192 + set * 64 + 32 + lane] = lk(o[j][1]);
        }
    }
}

// ---------------- per-node gate scalars, layer 2 (D=192) ----------------
__global__ void k_gate2(const float* __restrict__ w0, const float* __restrict__ w1,
                        const float* __restrict__ w2) {
    int gt = blockIdx.x * blockDim.x + threadIdx.x;
    int warp = gt >> 5, lane = gt & 31;
    int nw = (gridDim.x * blockDim.x) >> 5;
    for (int n = warp; n < Nn; n += nw) {
        float r[6];
        #pragma unroll
        for (int t = 0; t < 6; t++) r[t] = g_raw2[(long)n * 192 + lane + 32 * t];
        #pragma unroll
        for (int g = 0; g < 3; g++) {
            const float* w = g == 0 ? w0 : g == 1 ? w1 : w2;
            float pd = 0.f, ps = 0.f;
            #pragma unroll
            for (int t = 0; t < 6; t++) {
                pd = fmaf(r[t], w[lane + 32 * t], pd);
                ps = fmaf(r[t], w[192 + lane + 32 * t], ps);
            }
            #pragma unroll
            for (int off = 16; off; off >>= 1) {
                pd += __shfl_down_sync(0xFFFFFFFFu, pd, off);
                ps += __shfl_down_sync(0xFFFFFFFFu, ps, off);
            }
            if (lane == 0) {
                g_s2dst[g][n] = pd;
                g_sd2[g][n] = make_float2(ps, g_d[g][n]);
            }
        }
    }
}

// ------ fused layer-2 for SELECTED nodes: bucket gather + hw2 -> final ------
__global__ void k_final_h2(const int* __restrict__ nodes,
                           const float* __restrict__ hw0, const float* __restrict__ hw1p,
                           const float* __restrict__ hw2p, const float* __restrict__ b1,
                           const float* __restrict__ b2, const float* __restrict__ b3) {
    extern __shared__ float sm[];
    float* sW = sm;             // [192][64]
    float* su = sm + 12288;     // [8][192]
    int i = blockIdx.y;
    const float* w = i == 0 ? hw0 : i == 1 ? hw1p : hw2p;
    float gb = (i == 0 ? b1 : i == 1 ? b2 : b3)[0];
    int tid = threadIdx.x;
    for (int idx = tid; idx < 12288; idx += 256) sW[idx] = w[idx];
    __syncthreads();
    int warp = tid >> 5, lane = tid & 31;
    int b = blockIdx.x * 8 + warp;
    int n = nodes[b];
    int deg = min(g_deg[i][n], MAXDEG);
    int off = n * MAXDEG;
    float sd = g_s2dst[i][n] + gb;
    float ddn = g_d[i][n];
    float acc[6] = {};
    for (int base = 0; base < deg; base += 32) {
        int jj = base + lane;
        int src = 0;
        float e = 0.f;
        if (jj < deg) {
            src = __ldg(&g_esrc[i][off + jj]);
            float2 sv = g_sd2[i][src];
            e = tanhf(sd + sv.x) * ddn * sv.y;
        }
        int m = min(32, deg - base);
        for (int t = 0; t < m; t++) {
            float ee = __shfl_sync(0xFFFFFFFFu, e, t);
            int sj = __shfl_sync(0xFFFFFFFFu, src, t);
            const float* rp = g_raw2 + (long)sj * 192 + lane;
            #pragma unroll
            for (int q = 0; q < 6; q++)
                acc[q] = fmaf(ee, rp[q * 32], acc[q]);
        }
    }
    #pragma unroll
    for (int q = 0; q < 6; q++) {
        int k = lane + 32 * q;
        su[warp * 192 + k] = EPSc * g_raw2[(long)n * 192 + k] + acc[q];
    }
    __syncwarp();
    float a0 = 0.f, a1 = 0.f;
    #pragma unroll 8
    for (int k = 0; k < 192; k++) {
        float uk = su[warp * 192 + k];
        a0 = fmaf(uk, sW[k * 64 + lane], a0);
        a1 = fmaf(uk, sW[k * 64 + 32 + lane], a1);
    }
    g_final[(long)b * 192 + i * 64 + lane] = lk(a0);
    g_final[(long)b * 192 + i * 64 + 32 + lane] = lk(a1);
}

// ------ s64 = leaky(final @ t2_w^T + b) + fused scores, fused column gather --
__global__ void k_s64(const int* __restrict__ nodes, const float* __restrict__ h,
                      const float* __restrict__ t2w, const float* __restrict__ t2b,
                      const float* __restrict__ t3w, const float* __restrict__ t3b,
                      float* __restrict__ out, int outok) {
    __shared__ float As[32][32];
    __shared__ float Bs[32][65];
    __shared__ float sv[32][65];
    __shared__ int sn[32];
    int tid = threadIdx.x;
    int c = tid & 63, rg = tid >> 6;
    int rows0 = blockIdx.x * 32;
    if (tid < 32) sn[tid] = nodes[rows0 + tid];
    __syncthreads();
    float acc[8];
    #pragma unroll
    for (int r = 0; r < 8; r++) acc[r] = 0.f;
    for (int k0 = 0; k0 < 704; k0 += 32) {
        for (int idx = tid; idx < 1024; idx += 256) {
            int r = idx >> 5, kk = idx & 31;
            float v;
            if (k0 < 192)      v = g_final[(long)(rows0 + r) * 192 + k0 + kk];
            else if (k0 < 448) v = h[(long)sn[r] * 256 + (k0 - 192) + kk];
            else if (k0 < 512) v = g_x[(long)sn[r] * 64 + (k0 - 448) + kk];
            else               v = g_raw2[(long)sn[r] * 192 + (k0 - 512) + kk];
            As[r][kk] = v;
        }
        for (int idx = tid; idx < 2048; idx += 256) {
            int cc = idx >> 5, kk = idx & 31;
            Bs[kk][cc] = t2w[(long)cc * 704 + k0 + kk];
        }
        __syncthreads();
        #pragma unroll 8
        for (int kk = 0; kk < 32; kk++) {
            float bv = Bs[kk][c];
            #pragma unroll
            for (int r = 0; r < 8; r++) acc[r] = fmaf(As[rg * 8 + r][kk], bv, acc[r]);
        }
        __syncthreads();
    }
    float bias = t2b[c];
    #pragma unroll
    for (int r = 0; r < 8; r++) {
        int row = rows0 + rg * 8 + r;
        float v = lk(acc[r] + bias);
        sv[rg * 8 + r][c] = v;
        if (outok) out[8192 + (long)row * 64 + c] = v;
    }
    __syncthreads();
    int warp = tid >> 5, lane = tid & 31;
    for (int r = warp; r < 32; r += 8) {
        float v0 = sv[r][lane], v1 = sv[r][32 + lane];
        float p0 = v0 * t3w[lane] + v1 * t3w[32 + lane];
        float p1 = v0 * t3w[64 + lane] + v1 * t3w[96 + lane];
        #pragma unroll
        for (int off = 16; off; off >>= 1) {
            p0 += __shfl_down_sync(0xFFFFFFFFu, p0, off);
            p1 += __shfl_down_sync(0xFFFFFFFFu, p1, off);
        }
        if (lane == 0 && outok) {
            out[(rows0 + r) * 2]     = p0 + t3b[0];
            out[(rows0 + r) * 2 + 1] = p1 + t3b[1];
        }
    }
}

// ------ tail: re-zero degree counters so the next run starts clean ---------
__global__ void k_ztail() {
    int i = blockIdx.x * blockDim.x + threadIdx.x;
    int stride = gridDim.x * blockDim.x;
    int* dp = &g_deg[0][0];
    for (int j = i; j < 3 * Nn; j += stride) dp[j] = 0;
}

// ============================ host launcher ============================
extern "C" void kernel_launch(void* const* d_in, const int* in_sizes, int n_in,
                              void* d_out, int out_size) {
    auto f  = [&](int i) { return (const float*)d_in[i]; };
    auto ip = [&](int i) { return (const int*)d_in[i]; };
    bool dict = (n_in > 1 && in_sizes[1] == Ee);

    const float *h, *t1w, *t1b, *t2w, *t2b, *t3w, *t3b;
    const float *gw1[3], *gb1[3], *hw1[3], *gw2[3], *gb2[3], *hw2[3];
    const int *src[3], *dst[3], *nodes;
    h = f(0);
    if (dict) {
        src[0] = ip(1); dst[0] = ip(2);
        src[1] = ip(3); dst[1] = ip(4);
        src[2] = ip(5); dst[2] = ip(6);
        nodes = ip(7);
        t1w = f(8); t1b = f(9);
        for (int i = 0; i < 3; i++) {
            int b0 = 10 + i * 6;
            gw1[i] = f(b0);     gb1[i] = f(b0 + 1); hw1[i] = f(b0 + 2);
            gw2[i] = f(b0 + 3); gb2[i] = f(b0 + 4); hw2[i] = f(b0 + 5);
        }
        t2w = f(28); t2b = f(29); t3w = f(30); t3b = f(31);
    } else {
        t1w = f(1); t1b = f(2);
        for (int i = 0; i < 3; i++) {
            gw1[i] = f(3 + i * 3);  gb1[i] = f(4 + i * 3);  hw1[i] = f(5 + i * 3);
            gw2[i] = f(12 + i * 3); gb2[i] = f(13 + i * 3); hw2[i] = f(14 + i * 3);
        }
        t2w = f(21); t2b = f(22); t3w = f(23); t3b = f(24);
        src[0] = ip(25); dst[0] = ip(26);
        src[1] = ip(27); dst[1] = ip(28);
        src[2] = ip(29); dst[2] = ip(30);
        nodes = ip(31);
    }
    float* out = (float*)d_out;
    int out_full = (out_size >= Bb * 2 + Bb * 64) ? 1 : 0;

    int t1_smem = (32 * SH_STR + 32 * SW_STR) * 4;
    cudaFuncSetAttribute(k_t1,       cudaFuncAttributeMaxDynamicSharedMemorySize, t1_smem);
    cudaFuncSetAttribute(k_layer1,   cudaFuncAttributeMaxDynamicSharedMemorySize, 24576);
    cudaFuncSetAttribute(k_final_h2, cudaFuncAttributeMaxDynamicSharedMemorySize, 55296);

    k_fillpad<<<2048, 256>>>(src[0], dst[0], src[1], dst[1], src[2], dst[2]);
    k_t1<<<(Nn + 127) / 128, 256, t1_smem>>>(h, t1w, t1b);
    k_gate1<<<256, 256>>>(gw1[0], gw1[1], gw1[2]);
    dim3 gl1((Nn + 31) / 32, 3);
    k_layer1<<<gl1, 256, 24576>>>(hw1[0], hw1[1], hw1[2],
                                  gb1[0], gb1[1], gb1[2]);   // launch #4 -> ncu
    k_gate2<<<256, 256>>>(gw2[0], gw2[1], gw2[2]);
    dim3 gfh(Bb / 8, 3);
    k_final_h2<<<gfh, 256, 55296>>>(nodes, hw2[0], hw2[1], hw2[2],
                                    gb2[0], gb2[1], gb2[2]);
    k_s64<<<Bb / 32, 256>>>(nodes, h, t2w, t2b, t3w, t3b, out, out_full);
    k_ztail<<<128, 256>>>();
}